// round 13
// baseline (speedup 1.0000x reference)
#include <cuda_runtime.h>
#include <cuda_bf16.h>
#include <cstdint>

#define BB 8
#define NN 20000
#define GG 300
#define CC 80
#define KK 4
#define MAXPOS 128
#define CAP 512          // anchors per (b,class): mean 250, sigma 15.7
#define GCAP 64          // gts per (b,class): mean 3.75
#define LIM 4096         // stored-IoU matrix capacity (u32)
#define T_HIGH_F 0.7f

__device__ __forceinline__ unsigned encf(float f) {
    unsigned u = __float_as_uint(f);
    return (u & 0x80000000u) ? ~u : (u | 0x80000000u);
}
__device__ __forceinline__ float decf(unsigned e) {   // exact for iou >= 0
    return __uint_as_float(e & 0x7fffffffu);
}

// ---------------- global bins (cursor reset by K2 each replay) ----------------
__device__ int    g_cursor[BB * CC];      // zero-init; K2 re-zeroes every run
__device__ int    g_bidx[BB * CC * CAP];
__device__ float4 g_bbox[BB * CC * CAP];

// IoU: explicit *_rn intrinsics -> no FMA contraction -> bit-identical at
// every call site (the low-quality-match test is exact float equality).
__device__ __forceinline__ float iou_ga(float4 g, float garea, float4 a) {
    float hw = __fmul_rn(0.5f, a.z);
    float hh = __fmul_rn(0.5f, a.w);
    float ax1 = __fsub_rn(a.x, hw), ay1 = __fsub_rn(a.y, hh);
    float ax2 = __fadd_rn(a.x, hw), ay2 = __fadd_rn(a.y, hh);
    float aarea = __fmul_rn(__fsub_rn(ax2, ax1), __fsub_rn(ay2, ay1));
    float ltx = fmaxf(g.x, ax1), lty = fmaxf(g.y, ay1);
    float rbx = fminf(g.z, ax2), rby = fminf(g.w, ay2);
    float w = fmaxf(__fsub_rn(rbx, ltx), 0.0f);
    float h = fmaxf(__fsub_rn(rby, lty), 0.0f);
    float inter = __fmul_rn(w, h);
    float uni = __fsub_rn(__fadd_rn(garea, aarea), inter);
    return __fdiv_rn(inter, uni);
}

__device__ __forceinline__ bool better(float v1, int i1, float v2, int i2) {
    return (v1 > v2) || (v1 == v2 && i1 < i2);
}

// compare-exchange: keep the better pair in (va, ia)  [static indices only]
#define CASX(va, ia, vb, ib) do {                                   \
        bool _sw = better(vb, ib, va, ia);                          \
        float _tv = _sw ? vb : va; vb = _sw ? va : vb; va = _tv;    \
        int   _ti = _sw ? ib : ia; ib = _sw ? ia : ib; ia = _ti;    \
    } while (0)

// ---------------- K1: one-pass partition of anchors into (b,class) bins ----------------
__global__ void __launch_bounds__(256)
k_scatter(const float* __restrict__ anchors, const int* __restrict__ prompt_inds) {
    const int b = blockIdx.y;
    const int i4 = blockIdx.x * 256 + threadIdx.x;
    if (i4 >= NN / 4) return;
    int4 p = ((const int4*)&prompt_inds[b * NN])[i4];
    const int n0 = i4 * 4;
#define SCAT(cls, nn) do {                                                     \
        int q = atomicAdd(&g_cursor[b * CC + (cls)], 1);                       \
        if (q < CAP) {                                                         \
            int slot = (b * CC + (cls)) * CAP + q;                             \
            g_bidx[slot] = (nn);                                               \
            g_bbox[slot] = ((const float4*)anchors)[b * NN + (nn)];            \
        }                                                                      \
    } while (0)
    SCAT(p.x, n0);
    SCAT(p.y, n0 + 1);
    SCAT(p.z, n0 + 2);
    SCAT(p.w, n0 + 3);
#undef SCAT
}

// ---------------- K2: one block per (b,class) — scan-free assignment ----------------
__global__ void __launch_bounds__(256, 5)
k_assign(const int* __restrict__ tgt_labels, const float* __restrict__ tgt_boxes,
         float* __restrict__ out) {
    const int bid = blockIdx.x;            // 0 .. BB*CC-1
    const int b = bid / CC, c = bid % CC;
    const int t = threadIdx.x;
    const int lane = t & 31, wid = t >> 5;

    __shared__ int      s_gc, s_pos;
    __shared__ int      s_idx[CAP];
    __shared__ float4   s_box[CAP];
    __shared__ unsigned s_iou[LIM];        // encoded IoU, [i * S + j], S = Gc|1
    __shared__ unsigned char s_posf[CAP];
    __shared__ unsigned char s_bestj[CAP];
    __shared__ int      s_gid[GCAP];
    __shared__ float4   s_gxy[GCAP];
    __shared__ float    s_garea[GCAP];
    __shared__ unsigned s_gmax[GCAP];
    __shared__ int      s_gcnt[GCAP];

    if (t == 0) { s_gc = 0; s_pos = 0; }
    if (t < GCAP) { s_gmax[t] = 0u; s_gcnt[t] = 0; }
    __syncthreads();

    // ---- 1. gt list for this class (unordered compaction; every later
    //        tie-break uses the explicit gt id, so order never matters) ----
    for (int g = t; g < GG; g += 256) {
        if (tgt_labels[b * GG + g] == c) {
            int j = atomicAdd(&s_gc, 1);
            if (j < GCAP) {
                float4 bx = ((const float4*)tgt_boxes)[b * GG + g];
                float hw = __fmul_rn(0.5f, bx.z), hh = __fmul_rn(0.5f, bx.w);
                float4 xy = make_float4(__fsub_rn(bx.x, hw), __fsub_rn(bx.y, hh),
                                        __fadd_rn(bx.x, hw), __fadd_rn(bx.y, hh));
                s_gid[j]   = g;
                s_gxy[j]   = xy;
                s_garea[j] = __fmul_rn(__fsub_rn(xy.z, xy.x), __fsub_rn(xy.w, xy.y));
            }
        }
    }

    // ---- 2. load this bin (coalesced; <= 2 iterations) ----
    const int mraw = g_cursor[bid];
    const int m = min(mraw, CAP);
    for (int i = t; i < m; i += 256) {
        s_idx[i] = g_bidx[bid * CAP + i];
        s_box[i] = g_bbox[bid * CAP + i];
    }
    __syncthreads();
    // reset own cursor for the next replay (stream-ordered before next K1)
    if (t == 0) g_cursor[bid] = 0;

    const int Gc = min(s_gc, GCAP);
    if (Gc == 0) return;       // this block owns no gts -> no outputs

    const int S = Gc | 1;                  // odd stride -> conflict-free smem
    const bool stored = (m * S <= LIM);    // recompute fallback (never hit here)

    // ---- 3. row scan: each IoU computed ONCE; per-gt max via smem atomics;
    //         explicit two slots (no local arrays) ----
    float best0 = -1.0f, best1 = -1.0f;
#define ROW_SCAN(ii, bestv) do {                                              \
        float4 a = s_box[ii];                                                 \
        float bv = -1.0f;                                                     \
        int bj = 0, bgid = 0x7fffffff;                                        \
        for (int j = 0; j < Gc; j++) {                                        \
            float v = iou_ga(s_gxy[j], s_garea[j], a);                        \
            unsigned ev = encf(v);                                            \
            if (stored) s_iou[(ii) * S + j] = ev;                             \
            atomicMax(&s_gmax[j], ev);                                        \
            int gj = s_gid[j];                                                \
            if (v > bv || (v == bv && gj < bgid)) { bv = v; bj = j; bgid = gj; } \
        }                                                                     \
        bestv = bv;                                                           \
        s_bestj[ii] = (unsigned char)bj;                                      \
    } while (0)
    if (t < m)       ROW_SCAN(t, best0);
    if (t + 256 < m) ROW_SCAN(t + 256, best1);
#undef ROW_SCAN
    __syncthreads();

    // ---- 4. positivity + counts (lq test = stored bit equality) ----
#define POS_SCAN(ii, bestv) do {                                              \
        bool pos = (bestv >= T_HIGH_F);                                       \
        if (!pos) {                                                           \
            if (stored) {                                                     \
                for (int j = 0; j < Gc; j++)                                  \
                    if (s_iou[(ii) * S + j] == s_gmax[j]) { pos = true; break; } \
            } else {                                                          \
                float4 a = s_box[ii];                                         \
                unsigned eb = encf(bestv);                                    \
                for (int j = 0; j < Gc; j++) {                                \
                    unsigned gm = s_gmax[j];                                  \
                    if (eb >= gm &&                                           \
                        encf(iou_ga(s_gxy[j], s_garea[j], a)) == gm) {        \
                        pos = true; break; }                                  \
                }                                                             \
            }                                                                 \
        }                                                                     \
        s_posf[ii] = pos ? 1 : 0;                                             \
        if (pos) {                                                            \
            atomicAdd(&s_pos, 1);                                             \
            atomicAdd(&s_gcnt[s_bestj[ii]], 1);                               \
        }                                                                     \
    } while (0)
    if (t < m)       POS_SCAN(t, best0);
    if (t + 256 < m) POS_SCAN(t + 256, best1);
#undef POS_SCAN
    __syncthreads();

    // ---- 5. rare MAX_POS fixup (warp 0; order-independent binary search
    //        for the MAXPOS-th smallest positive anchor id) ----
    if (s_pos > MAXPOS && wid == 0) {
        int lo = 0, hi = NN - 1;
        while (lo < hi) {
            int mid = (lo + hi) >> 1;
            int cnt = 0;
            for (int i = lane; i < m; i += 32)
                if (s_posf[i] && s_idx[i] <= mid) cnt++;
            cnt = __reduce_add_sync(0xffffffffu, cnt);
            if (cnt >= MAXPOS) hi = mid; else lo = mid + 1;
        }
        for (int j = 0; j < Gc; j++) {
            int keep = 0;
            for (int i = lane; i < m; i += 32)
                if (s_posf[i] && s_idx[i] <= lo && s_bestj[i] == j) keep++;
            keep = __reduce_add_sync(0xffffffffu, keep);
            if (lane == 0) s_gcnt[j] = keep;
        }
    }
    __syncthreads();

    // ---- 6. top-4 per gt: one warp per gt; static-index CAS merge ----
    const int P = BB * GG * KK;
    for (int j = wid; j < Gc; j += 8) {
        float v0 = -1e30f, v1 = -1e30f, v2 = -1e30f, v3 = -1e30f;
        int   i0 = 0x7fffffff, i1 = 0x7fffffff, i2 = 0x7fffffff, i3 = 0x7fffffff;
#define INSERT(val, n) do {                                                   \
        if (better(val, n, v3, i3)) {                                         \
            v3 = val; i3 = n;                                                 \
            if (better(v3, i3, v2, i2)) { float tv=v2;int ti=i2; v2=v3;i2=i3; v3=tv;i3=ti; } \
            if (better(v2, i2, v1, i1)) { float tv=v1;int ti=i1; v1=v2;i1=i2; v2=tv;i2=ti; } \
            if (better(v1, i1, v0, i0)) { float tv=v0;int ti=i0; v0=v1;i0=i1; v1=tv;i1=ti; } \
        }                                                                     \
    } while (0)
        if (stored) {
            for (int i = lane; i < m; i += 32) {
                float val = decf(s_iou[i * S + j]);
                INSERT(val, s_idx[i]);
            }
        } else {
            float4 gx = s_gxy[j];
            float ga = s_garea[j];
            for (int i = lane; i < m; i += 32) {
                float val = iou_ga(gx, ga, s_box[i]);
                INSERT(val, s_idx[i]);
            }
        }
#undef INSERT
        // butterfly merge: bitonic half-cleaner + 4-sort, all static indices
#pragma unroll
        for (int off = 16; off >= 1; off >>= 1) {
            float b0 = __shfl_xor_sync(0xffffffffu, v0, off);
            float b1 = __shfl_xor_sync(0xffffffffu, v1, off);
            float b2 = __shfl_xor_sync(0xffffffffu, v2, off);
            float b3 = __shfl_xor_sync(0xffffffffu, v3, off);
            int   c0 = __shfl_xor_sync(0xffffffffu, i0, off);
            int   c1 = __shfl_xor_sync(0xffffffffu, i1, off);
            int   c2 = __shfl_xor_sync(0xffffffffu, i2, off);
            int   c3 = __shfl_xor_sync(0xffffffffu, i3, off);
            if (better(b3, c3, v0, i0)) { v0 = b3; i0 = c3; }
            if (better(b2, c2, v1, i1)) { v1 = b2; i1 = c2; }
            if (better(b1, c1, v2, i2)) { v2 = b1; i2 = c1; }
            if (better(b0, c0, v3, i3)) { v3 = b0; i3 = c0; }
            CASX(v0, i0, v2, i2);
            CASX(v1, i1, v3, i3);
            CASX(v0, i0, v1, i1);
            CASX(v2, i2, v3, i3);
        }
        int kk = min(s_gcnt[j], KK);
        int g = s_gid[j];
        if (lane == 0) {
            int o = (b * GG + g) * KK;
            float ov[KK] = {v0, v1, v2, v3};
            int   oi[KK] = {i0, i1, i2, i3};
#pragma unroll
            for (int k = 0; k < KK; k++) {
                bool valid = (k < kk);
                out[o + k]         = valid ? (float)oi[k] : -1.0f;
                out[P + o + k]     = valid ? (float)g     : -1.0f;
                out[2 * P + o + k] = valid ? 1.0f : 0.0f;
                out[3 * P + o + k] = valid ? ov[k] : 0.0f;
            }
        }
    }
}

// ---------------- launch ----------------
extern "C" void kernel_launch(void* const* d_in, const int* in_sizes, int n_in,
                              void* d_out, int out_size) {
    (void)in_sizes; (void)n_in; (void)out_size;
    const float* anchors     = (const float*)d_in[2];
    const int*   prompt_inds = (const int*)d_in[3];
    const int*   tgt_labels  = (const int*)d_in[4];
    const float* tgt_boxes   = (const float*)d_in[5];
    float* out = (float*)d_out;

    dim3 gscat((NN / 4 + 255) / 256, BB);      // 20 x 8 = 160 blocks
    k_scatter<<<gscat, 256>>>(anchors, prompt_inds);
    k_assign<<<BB * CC, 256>>>(tgt_labels, tgt_boxes, out);
}

// round 14
// speedup vs baseline: 1.0253x; 1.0253x over previous
#include <cuda_runtime.h>
#include <cuda_bf16.h>
#include <cstdint>

#define BB 8
#define NN 20000
#define GG 300
#define CC 80
#define KK 4
#define MAXPOS 128
#define CAP 512          // anchors per (b,class): mean 250, sigma 15.7
#define GCAP 64          // gts per (b,class): mean 3.75
#define LIM 4096         // stored-IoU matrix capacity (u32)
#define T_HIGH_F 0.7f

__device__ __forceinline__ unsigned encf(float f) {
    unsigned u = __float_as_uint(f);
    return (u & 0x80000000u) ? ~u : (u | 0x80000000u);
}
__device__ __forceinline__ float decf(unsigned e) {   // exact for iou >= 0
    return __uint_as_float(e & 0x7fffffffu);
}

// ---------------- global bins (cursor reset by K2 each replay) ----------------
__device__ int g_cursor[BB * CC];      // zero-init; K2 re-zeroes every run
__device__ int g_bidx[BB * CC * CAP];

// IoU: explicit *_rn intrinsics -> no FMA contraction -> bit-identical at
// every call site (the low-quality-match test is exact float equality).
__device__ __forceinline__ float iou_ga(float4 g, float garea, float4 a) {
    float hw = __fmul_rn(0.5f, a.z);
    float hh = __fmul_rn(0.5f, a.w);
    float ax1 = __fsub_rn(a.x, hw), ay1 = __fsub_rn(a.y, hh);
    float ax2 = __fadd_rn(a.x, hw), ay2 = __fadd_rn(a.y, hh);
    float aarea = __fmul_rn(__fsub_rn(ax2, ax1), __fsub_rn(ay2, ay1));
    float ltx = fmaxf(g.x, ax1), lty = fmaxf(g.y, ay1);
    float rbx = fminf(g.z, ax2), rby = fminf(g.w, ay2);
    float w = fmaxf(__fsub_rn(rbx, ltx), 0.0f);
    float h = fmaxf(__fsub_rn(rby, lty), 0.0f);
    float inter = __fmul_rn(w, h);
    float uni = __fsub_rn(__fadd_rn(garea, aarea), inter);
    return __fdiv_rn(inter, uni);
}

__device__ __forceinline__ bool better(float v1, int i1, float v2, int i2) {
    return (v1 > v2) || (v1 == v2 && i1 < i2);
}

// compare-exchange: keep the better pair in (va, ia)  [static indices only]
#define CASX(va, ia, vb, ib) do {                                   \
        bool _sw = better(vb, ib, va, ia);                          \
        float _tv = _sw ? vb : va; vb = _sw ? va : vb; va = _tv;    \
        int   _ti = _sw ? ib : ia; ib = _sw ? ia : ib; ia = _ti;    \
    } while (0)

// ---------------- K1: one-pass index-only partition into (b,class) bins ----------------
__global__ void __launch_bounds__(256)
k_scatter(const int* __restrict__ prompt_inds) {
    const int b = blockIdx.y;
    const int i4 = blockIdx.x * 256 + threadIdx.x;
    if (i4 >= NN / 4) return;
    int4 p = ((const int4*)&prompt_inds[b * NN])[i4];
    const int n0 = i4 * 4;
#define SCAT(cls, nn) do {                                                     \
        int q = atomicAdd(&g_cursor[b * CC + (cls)], 1);                       \
        if (q < CAP) g_bidx[(b * CC + (cls)) * CAP + q] = (nn);                \
    } while (0)
    SCAT(p.x, n0);
    SCAT(p.y, n0 + 1);
    SCAT(p.z, n0 + 2);
    SCAT(p.w, n0 + 3);
#undef SCAT
}

// ---------------- K2: one block per (b,class) — PDL-overlapped assignment ----------------
__global__ void __launch_bounds__(256, 5)
k_assign(const float* __restrict__ anchors, const int* __restrict__ tgt_labels,
         const float* __restrict__ tgt_boxes, float* __restrict__ out) {
    const int bid = blockIdx.x;            // 0 .. BB*CC-1
    const int b = bid / CC, c = bid % CC;
    const int t = threadIdx.x;
    const int lane = t & 31, wid = t >> 5;

    __shared__ int      s_gc, s_pos;
    __shared__ int      s_idx[CAP];
    __shared__ float4   s_box[CAP];        // fallback only
    __shared__ unsigned s_iou[LIM];        // encoded IoU, [i * S + j], S = Gc|1
    __shared__ unsigned char s_posf[CAP];
    __shared__ unsigned char s_bestj[CAP];
    __shared__ int      s_gid[GCAP];
    __shared__ float4   s_gxy[GCAP];
    __shared__ float    s_garea[GCAP];
    __shared__ unsigned s_gmax[GCAP];
    __shared__ int      s_gcnt[GCAP];

    if (t == 0) { s_gc = 0; s_pos = 0; }
    if (t < GCAP) { s_gmax[t] = 0u; s_gcnt[t] = 0; }
    __syncthreads();

    // ---- 1. gt list (INDEPENDENT of K1 -> runs under PDL overlap) ----
    for (int g = t; g < GG; g += 256) {
        if (tgt_labels[b * GG + g] == c) {
            int j = atomicAdd(&s_gc, 1);
            if (j < GCAP) {
                float4 bx = ((const float4*)tgt_boxes)[b * GG + g];
                float hw = __fmul_rn(0.5f, bx.z), hh = __fmul_rn(0.5f, bx.w);
                float4 xy = make_float4(__fsub_rn(bx.x, hw), __fsub_rn(bx.y, hh),
                                        __fadd_rn(bx.x, hw), __fadd_rn(bx.y, hh));
                s_gid[j]   = g;
                s_gxy[j]   = xy;
                s_garea[j] = __fmul_rn(__fsub_rn(xy.z, xy.x), __fsub_rn(xy.w, xy.y));
            }
        }
    }

    // ---- wait for K1's bins to be visible ----
    cudaGridDependencySynchronize();

    // ---- 2. load this bin's indices (coalesced; <= 2 iterations) ----
    const int mraw = g_cursor[bid];
    const int m = min(mraw, CAP);
    for (int i = t; i < m; i += 256)
        s_idx[i] = g_bidx[bid * CAP + i];
    __syncthreads();
    if (t == 0) g_cursor[bid] = 0;     // reset for next replay (stream-ordered)

    const int Gc = min(s_gc, GCAP);
    if (Gc == 0) return;               // no gts of this class -> no outputs

    const int S = Gc | 1;              // odd stride -> conflict-free smem
    const bool stored = (m * S <= LIM);
    if (!stored) {                     // fallback path only (never hit here)
        for (int i = t; i < m; i += 256)
            s_box[i] = ((const float4*)anchors)[b * NN + s_idx[i]];
        __syncthreads();
    }

    // ---- 3. row scan: own anchor box straight to registers; IoU ONCE ----
    float best0 = -1.0f, best1 = -1.0f;
#define ROW_SCAN(ii, bestv) do {                                              \
        float4 a = ((const float4*)anchors)[b * NN + s_idx[ii]];              \
        float bv = -1.0f;                                                     \
        int bj = 0, bgid = 0x7fffffff;                                        \
        for (int j = 0; j < Gc; j++) {                                        \
            float v = iou_ga(s_gxy[j], s_garea[j], a);                        \
            unsigned ev = encf(v);                                            \
            if (stored) s_iou[(ii) * S + j] = ev;                             \
            atomicMax(&s_gmax[j], ev);                                        \
            int gj = s_gid[j];                                                \
            if (v > bv || (v == bv && gj < bgid)) { bv = v; bj = j; bgid = gj; } \
        }                                                                     \
        bestv = bv;                                                           \
        s_bestj[ii] = (unsigned char)bj;                                      \
    } while (0)
    if (t < m)       ROW_SCAN(t, best0);
    if (t + 256 < m) ROW_SCAN(t + 256, best1);
#undef ROW_SCAN
    __syncthreads();

    // ---- 4. positivity + counts (lq test = stored bit equality) ----
#define POS_SCAN(ii, bestv) do {                                              \
        bool pos = (bestv >= T_HIGH_F);                                       \
        if (!pos) {                                                           \
            if (stored) {                                                     \
                for (int j = 0; j < Gc; j++)                                  \
                    if (s_iou[(ii) * S + j] == s_gmax[j]) { pos = true; break; } \
            } else {                                                          \
                float4 a = s_box[ii];                                         \
                unsigned eb = encf(bestv);                                    \
                for (int j = 0; j < Gc; j++) {                                \
                    unsigned gm = s_gmax[j];                                  \
                    if (eb >= gm &&                                           \
                        encf(iou_ga(s_gxy[j], s_garea[j], a)) == gm) {        \
                        pos = true; break; }                                  \
                }                                                             \
            }                                                                 \
        }                                                                     \
        s_posf[ii] = pos ? 1 : 0;                                             \
        if (pos) {                                                            \
            atomicAdd(&s_pos, 1);                                             \
            atomicAdd(&s_gcnt[s_bestj[ii]], 1);                               \
        }                                                                     \
    } while (0)
    if (t < m)       POS_SCAN(t, best0);
    if (t + 256 < m) POS_SCAN(t + 256, best1);
#undef POS_SCAN
    __syncthreads();

    // ---- 5. rare MAX_POS fixup (warp 0; order-independent binary search) ----
    if (s_pos > MAXPOS && wid == 0) {
        int lo = 0, hi = NN - 1;
        while (lo < hi) {
            int mid = (lo + hi) >> 1;
            int cnt = 0;
            for (int i = lane; i < m; i += 32)
                if (s_posf[i] && s_idx[i] <= mid) cnt++;
            cnt = __reduce_add_sync(0xffffffffu, cnt);
            if (cnt >= MAXPOS) hi = mid; else lo = mid + 1;
        }
        for (int j = 0; j < Gc; j++) {
            int keep = 0;
            for (int i = lane; i < m; i += 32)
                if (s_posf[i] && s_idx[i] <= lo && s_bestj[i] == j) keep++;
            keep = __reduce_add_sync(0xffffffffu, keep);
            if (lane == 0) s_gcnt[j] = keep;
        }
    }
    __syncthreads();

    // ---- 6. top-4 per gt: one warp per gt; static-index CAS merge ----
    const int P = BB * GG * KK;
    for (int j = wid; j < Gc; j += 8) {
        float v0 = -1e30f, v1 = -1e30f, v2 = -1e30f, v3 = -1e30f;
        int   i0 = 0x7fffffff, i1 = 0x7fffffff, i2 = 0x7fffffff, i3 = 0x7fffffff;
#define INSERT(val, n) do {                                                   \
        if (better(val, n, v3, i3)) {                                         \
            v3 = val; i3 = n;                                                 \
            if (better(v3, i3, v2, i2)) { float tv=v2;int ti=i2; v2=v3;i2=i3; v3=tv;i3=ti; } \
            if (better(v2, i2, v1, i1)) { float tv=v1;int ti=i1; v1=v2;i1=i2; v2=tv;i2=ti; } \
            if (better(v1, i1, v0, i0)) { float tv=v0;int ti=i0; v0=v1;i0=i1; v1=tv;i1=ti; } \
        }                                                                     \
    } while (0)
        if (stored) {
            for (int i = lane; i < m; i += 32) {
                float val = decf(s_iou[i * S + j]);
                INSERT(val, s_idx[i]);
            }
        } else {
            float4 gx = s_gxy[j];
            float ga = s_garea[j];
            for (int i = lane; i < m; i += 32) {
                float val = iou_ga(gx, ga, s_box[i]);
                INSERT(val, s_idx[i]);
            }
        }
#undef INSERT
        // butterfly merge: bitonic half-cleaner + 4-sort, all static indices
#pragma unroll
        for (int off = 16; off >= 1; off >>= 1) {
            float b0 = __shfl_xor_sync(0xffffffffu, v0, off);
            float b1 = __shfl_xor_sync(0xffffffffu, v1, off);
            float b2 = __shfl_xor_sync(0xffffffffu, v2, off);
            float b3 = __shfl_xor_sync(0xffffffffu, v3, off);
            int   c0 = __shfl_xor_sync(0xffffffffu, i0, off);
            int   c1 = __shfl_xor_sync(0xffffffffu, i1, off);
            int   c2 = __shfl_xor_sync(0xffffffffu, i2, off);
            int   c3 = __shfl_xor_sync(0xffffffffu, i3, off);
            if (better(b3, c3, v0, i0)) { v0 = b3; i0 = c3; }
            if (better(b2, c2, v1, i1)) { v1 = b2; i1 = c2; }
            if (better(b1, c1, v2, i2)) { v2 = b1; i2 = c1; }
            if (better(b0, c0, v3, i3)) { v3 = b0; i3 = c0; }
            CASX(v0, i0, v2, i2);
            CASX(v1, i1, v3, i3);
            CASX(v0, i0, v1, i1);
            CASX(v2, i2, v3, i3);
        }
        int kk = min(s_gcnt[j], KK);
        int g = s_gid[j];
        if (lane == 0) {
            int o = (b * GG + g) * KK;
            float ov[KK] = {v0, v1, v2, v3};
            int   oi[KK] = {i0, i1, i2, i3};
#pragma unroll
            for (int k = 0; k < KK; k++) {
                bool valid = (k < kk);
                out[o + k]         = valid ? (float)oi[k] : -1.0f;
                out[P + o + k]     = valid ? (float)g     : -1.0f;
                out[2 * P + o + k] = valid ? 1.0f : 0.0f;
                out[3 * P + o + k] = valid ? ov[k] : 0.0f;
            }
        }
    }
}

// ---------------- launch: K1, then K2 with programmatic dependent launch ----------------
extern "C" void kernel_launch(void* const* d_in, const int* in_sizes, int n_in,
                              void* d_out, int out_size) {
    (void)in_sizes; (void)n_in; (void)out_size;
    const float* anchors     = (const float*)d_in[2];
    const int*   prompt_inds = (const int*)d_in[3];
    const int*   tgt_labels  = (const int*)d_in[4];
    const float* tgt_boxes   = (const float*)d_in[5];
    float* out = (float*)d_out;

    dim3 gscat((NN / 4 + 255) / 256, BB);      // 20 x 8 = 160 blocks
    k_scatter<<<gscat, 256>>>(prompt_inds);

    cudaLaunchConfig_t cfg = {};
    cfg.gridDim = dim3(BB * CC);
    cfg.blockDim = dim3(256);
    cfg.dynamicSmemBytes = 0;
    cfg.stream = 0;
    cudaLaunchAttribute attrs[1];
    attrs[0].id = cudaLaunchAttributeProgrammaticStreamSerialization;
    attrs[0].val.programmaticStreamSerializationAllowed = 1;
    cfg.attrs = attrs;
    cfg.numAttrs = 1;
    cudaLaunchKernelEx(&cfg, k_assign, anchors, tgt_labels, tgt_boxes, out);
}

// round 15
// speedup vs baseline: 1.2301x; 1.1997x over previous
#include <cuda_runtime.h>
#include <cuda_bf16.h>
#include <cstdint>

#define BB 8
#define NN 20000
#define GG 300
#define CC 80
#define KK 4
#define MAXPOS 128
#define CAP 512          // anchors per (b,class): mean 250, sigma 15.7
#define GCAP 64          // gts per (b,class): mean 3.75
#define LIM 4096         // stored-IoU matrix capacity (u32)
#define IPB 250          // ints per scatter slice (250 * 80 = NN)
#define NBLK (BB * CC)   // 640 blocks, all co-resident (740 slots at occ 5)
#define T_HIGH_F 0.7f

__device__ __forceinline__ unsigned encf(float f) {
    unsigned u = __float_as_uint(f);
    return (u & 0x80000000u) ? ~u : (u | 0x80000000u);
}
__device__ __forceinline__ float decf(unsigned e) {   // exact for iou >= 0
    return __uint_as_float(e & 0x7fffffffu);
}

// ---------------- global scratch ----------------
__device__ int g_cursor[BB * CC];      // zero-init; owner block re-zeroes each run
__device__ int g_bidx[BB * CC * CAP];
__device__ unsigned long long g_bar;   // monotone barrier counter (never reset)

// IoU: explicit *_rn intrinsics -> no FMA contraction -> bit-identical at
// every call site (the low-quality-match test is exact float equality).
__device__ __forceinline__ float iou_ga(float4 g, float garea, float4 a) {
    float hw = __fmul_rn(0.5f, a.z);
    float hh = __fmul_rn(0.5f, a.w);
    float ax1 = __fsub_rn(a.x, hw), ay1 = __fsub_rn(a.y, hh);
    float ax2 = __fadd_rn(a.x, hw), ay2 = __fadd_rn(a.y, hh);
    float aarea = __fmul_rn(__fsub_rn(ax2, ax1), __fsub_rn(ay2, ay1));
    float ltx = fmaxf(g.x, ax1), lty = fmaxf(g.y, ay1);
    float rbx = fminf(g.z, ax2), rby = fminf(g.w, ay2);
    float w = fmaxf(__fsub_rn(rbx, ltx), 0.0f);
    float h = fmaxf(__fsub_rn(rby, lty), 0.0f);
    float inter = __fmul_rn(w, h);
    float uni = __fsub_rn(__fadd_rn(garea, aarea), inter);
    return __fdiv_rn(inter, uni);
}

__device__ __forceinline__ bool better(float v1, int i1, float v2, int i2) {
    return (v1 > v2) || (v1 == v2 && i1 < i2);
}

// compare-exchange: keep the better pair in (va, ia)  [static indices only]
#define CASX(va, ia, vb, ib) do {                                   \
        bool _sw = better(vb, ib, va, ia);                          \
        float _tv = _sw ? vb : va; vb = _sw ? va : vb; va = _tv;    \
        int   _ti = _sw ? ib : ia; ib = _sw ? ia : ib; ia = _ti;    \
    } while (0)

__global__ void __launch_bounds__(256, 5)
k_fused(const float* __restrict__ anchors, const int* __restrict__ prompt_inds,
        const int* __restrict__ tgt_labels, const float* __restrict__ tgt_boxes,
        float* __restrict__ out) {
    const int bid = blockIdx.x;            // 0 .. NBLK-1
    const int b = bid / CC, c = bid % CC;  // assign role; c also = scatter slice
    const int t = threadIdx.x;
    const int lane = t & 31, wid = t >> 5;

    __shared__ int      s_cnt[CC], s_base[CC];
    __shared__ int      s_gc, s_pos;
    __shared__ int      s_idx[CAP];
    __shared__ unsigned s_iou[LIM];        // encoded IoU, [i * S + j], S = Gc|1
    __shared__ unsigned char s_posf[CAP];
    __shared__ unsigned char s_bestj[CAP];
    __shared__ int      s_gid[GCAP];
    __shared__ float4   s_gxy[GCAP];
    __shared__ float    s_garea[GCAP];
    __shared__ unsigned s_gmax[GCAP];
    __shared__ int      s_gcnt[GCAP];

    if (t < CC) s_cnt[t] = 0;
    if (t == 0) { s_gc = 0; s_pos = 0; }
    if (t < GCAP) { s_gmax[t] = 0u; s_gcnt[t] = 0; }
    __syncthreads();

    // ---- Phase S: scatter this block's 250-int slice into (b,class) bins ----
    int mycls = -1, myrank = 0;
    const int myn = c * IPB + t;           // anchor id within image b
    if (t < IPB) {
        mycls = prompt_inds[b * NN + myn];
        myrank = atomicAdd(&s_cnt[mycls], 1);
    }
    __syncthreads();
    if (t < CC && s_cnt[t] > 0)
        s_base[t] = atomicAdd(&g_cursor[b * CC + t], s_cnt[t]);
    __syncthreads();
    if (t < IPB) {
        int q = s_base[mycls] + myrank;
        if (q < CAP) g_bidx[(b * CC + mycls) * CAP + q] = myn;
    }

    // ---- Phase G: gt list (independent of scatter; hides barrier skew).
    //      Unordered compaction: every later tie-break uses explicit gt id. ----
    for (int g = t; g < GG; g += 256) {
        if (tgt_labels[b * GG + g] == c) {
            int j = atomicAdd(&s_gc, 1);
            if (j < GCAP) {
                float4 bx = ((const float4*)tgt_boxes)[b * GG + g];
                float hw = __fmul_rn(0.5f, bx.z), hh = __fmul_rn(0.5f, bx.w);
                float4 xy = make_float4(__fsub_rn(bx.x, hw), __fsub_rn(bx.y, hh),
                                        __fadd_rn(bx.x, hw), __fadd_rn(bx.y, hh));
                s_gid[j]   = g;
                s_gxy[j]   = xy;
                s_garea[j] = __fmul_rn(__fsub_rn(xy.z, xy.x), __fsub_rn(xy.w, xy.y));
            }
        }
    }

    // ---- grid barrier: monotone counter, all 640 blocks co-resident ----
    __threadfence();
    __syncthreads();
    if (t == 0) {
        unsigned long long old = atomicAdd(&g_bar, 1ull);
        unsigned long long target = (old / NBLK + 1ull) * (unsigned long long)NBLK;
        while (*(volatile unsigned long long*)&g_bar < target) { __nanosleep(32); }
        __threadfence();
    }
    __syncthreads();

    // ---- Phase A: load this bin's indices ----
    const int m = min(g_cursor[bid], CAP);
    for (int i = t; i < m; i += 256)
        s_idx[i] = g_bidx[bid * CAP + i];
    __syncthreads();
    if (t == 0) g_cursor[bid] = 0;     // owner-only; reset for next replay

    const int Gc = min(s_gc, GCAP);
    if (Gc == 0) return;               // safe: past the barrier

    const int S = Gc | 1;              // odd stride -> conflict-free smem
    const bool stored = (m * S <= LIM);

    // ---- row scan: own anchor box straight to registers; IoU ONCE ----
    float best0 = -1.0f, best1 = -1.0f;
#define ROW_SCAN(ii, bestv) do {                                              \
        float4 a = ((const float4*)anchors)[b * NN + s_idx[ii]];              \
        float bv = -1.0f;                                                     \
        int bj = 0, bgid = 0x7fffffff;                                        \
        for (int j = 0; j < Gc; j++) {                                        \
            float v = iou_ga(s_gxy[j], s_garea[j], a);                        \
            unsigned ev = encf(v);                                            \
            if (stored) s_iou[(ii) * S + j] = ev;                             \
            atomicMax(&s_gmax[j], ev);                                        \
            int gj = s_gid[j];                                                \
            if (v > bv || (v == bv && gj < bgid)) { bv = v; bj = j; bgid = gj; } \
        }                                                                     \
        bestv = bv;                                                           \
        s_bestj[ii] = (unsigned char)bj;                                      \
    } while (0)
    if (t < m)       ROW_SCAN(t, best0);
    if (t + 256 < m) ROW_SCAN(t + 256, best1);
#undef ROW_SCAN
    __syncthreads();

    // ---- positivity + counts (lq test = stored bit equality) ----
#define POS_SCAN(ii, bestv) do {                                              \
        bool pos = (bestv >= T_HIGH_F);                                       \
        if (!pos) {                                                           \
            if (stored) {                                                     \
                for (int j = 0; j < Gc; j++)                                  \
                    if (s_iou[(ii) * S + j] == s_gmax[j]) { pos = true; break; } \
            } else {                                                          \
                float4 a = ((const float4*)anchors)[b * NN + s_idx[ii]];      \
                unsigned eb = encf(bestv);                                    \
                for (int j = 0; j < Gc; j++) {                                \
                    unsigned gm = s_gmax[j];                                  \
                    if (eb >= gm &&                                           \
                        encf(iou_ga(s_gxy[j], s_garea[j], a)) == gm) {        \
                        pos = true; break; }                                  \
                }                                                             \
            }                                                                 \
        }                                                                     \
        s_posf[ii] = pos ? 1 : 0;                                             \
        if (pos) {                                                            \
            atomicAdd(&s_pos, 1);                                             \
            atomicAdd(&s_gcnt[s_bestj[ii]], 1);                               \
        }                                                                     \
    } while (0)
    if (t < m)       POS_SCAN(t, best0);
    if (t + 256 < m) POS_SCAN(t + 256, best1);
#undef POS_SCAN
    __syncthreads();

    // ---- rare MAX_POS fixup (warp 0; order-independent binary search) ----
    if (s_pos > MAXPOS && wid == 0) {
        int lo = 0, hi = NN - 1;
        while (lo < hi) {
            int mid = (lo + hi) >> 1;
            int cnt = 0;
            for (int i = lane; i < m; i += 32)
                if (s_posf[i] && s_idx[i] <= mid) cnt++;
            cnt = __reduce_add_sync(0xffffffffu, cnt);
            if (cnt >= MAXPOS) hi = mid; else lo = mid + 1;
        }
        for (int j = 0; j < Gc; j++) {
            int keep = 0;
            for (int i = lane; i < m; i += 32)
                if (s_posf[i] && s_idx[i] <= lo && s_bestj[i] == j) keep++;
            keep = __reduce_add_sync(0xffffffffu, keep);
            if (lane == 0) s_gcnt[j] = keep;
        }
    }
    __syncthreads();

    // ---- top-4 per gt: one warp per gt; static-index CAS merge ----
    const int P = BB * GG * KK;
    for (int j = wid; j < Gc; j += 8) {
        float v0 = -1e30f, v1 = -1e30f, v2 = -1e30f, v3 = -1e30f;
        int   i0 = 0x7fffffff, i1 = 0x7fffffff, i2 = 0x7fffffff, i3 = 0x7fffffff;
#define INSERT(val, n) do {                                                   \
        if (better(val, n, v3, i3)) {                                         \
            v3 = val; i3 = n;                                                 \
            if (better(v3, i3, v2, i2)) { float tv=v2;int ti=i2; v2=v3;i2=i3; v3=tv;i3=ti; } \
            if (better(v2, i2, v1, i1)) { float tv=v1;int ti=i1; v1=v2;i1=i2; v2=tv;i2=ti; } \
            if (better(v1, i1, v0, i0)) { float tv=v0;int ti=i0; v0=v1;i0=i1; v1=tv;i1=ti; } \
        }                                                                     \
    } while (0)
        if (stored) {
            for (int i = lane; i < m; i += 32) {
                float val = decf(s_iou[i * S + j]);
                INSERT(val, s_idx[i]);
            }
        } else {
            float4 gx = s_gxy[j];
            float ga = s_garea[j];
            for (int i = lane; i < m; i += 32) {
                float4 a = ((const float4*)anchors)[b * NN + s_idx[i]];
                float val = iou_ga(gx, ga, a);
                INSERT(val, s_idx[i]);
            }
        }
#undef INSERT
        // butterfly merge: bitonic half-cleaner + 4-sort, all static indices
#pragma unroll
        for (int off = 16; off >= 1; off >>= 1) {
            float b0 = __shfl_xor_sync(0xffffffffu, v0, off);
            float b1 = __shfl_xor_sync(0xffffffffu, v1, off);
            float b2 = __shfl_xor_sync(0xffffffffu, v2, off);
            float b3 = __shfl_xor_sync(0xffffffffu, v3, off);
            int   c0 = __shfl_xor_sync(0xffffffffu, i0, off);
            int   c1 = __shfl_xor_sync(0xffffffffu, i1, off);
            int   c2 = __shfl_xor_sync(0xffffffffu, i2, off);
            int   c3 = __shfl_xor_sync(0xffffffffu, i3, off);
            if (better(b3, c3, v0, i0)) { v0 = b3; i0 = c3; }
            if (better(b2, c2, v1, i1)) { v1 = b2; i1 = c2; }
            if (better(b1, c1, v2, i2)) { v2 = b1; i2 = c1; }
            if (better(b0, c0, v3, i3)) { v3 = b0; i3 = c0; }
            CASX(v0, i0, v2, i2);
            CASX(v1, i1, v3, i3);
            CASX(v0, i0, v1, i1);
            CASX(v2, i2, v3, i3);
        }
        int kk = min(s_gcnt[j], KK);
        int g = s_gid[j];
        if (lane == 0) {
            int o = (b * GG + g) * KK;
            float ov[KK] = {v0, v1, v2, v3};
            int   oi[KK] = {i0, i1, i2, i3};
#pragma unroll
            for (int k = 0; k < KK; k++) {
                bool valid = (k < kk);
                out[o + k]         = valid ? (float)oi[k] : -1.0f;
                out[P + o + k]     = valid ? (float)g     : -1.0f;
                out[2 * P + o + k] = valid ? 1.0f : 0.0f;
                out[3 * P + o + k] = valid ? ov[k] : 0.0f;
            }
        }
    }
}

// ---------------- launch: single fused kernel ----------------
extern "C" void kernel_launch(void* const* d_in, const int* in_sizes, int n_in,
                              void* d_out, int out_size) {
    (void)in_sizes; (void)n_in; (void)out_size;
    const float* anchors     = (const float*)d_in[2];
    const int*   prompt_inds = (const int*)d_in[3];
    const int*   tgt_labels  = (const int*)d_in[4];
    const float* tgt_boxes   = (const float*)d_in[5];
    float* out = (float*)d_out;

    k_fused<<<NBLK, 256>>>(anchors, prompt_inds, tgt_labels, tgt_boxes, out);
}

// round 16
// speedup vs baseline: 1.3365x; 1.0865x over previous
#include <cuda_runtime.h>
#include <cuda_bf16.h>
#include <cstdint>

#define BB 8
#define NN 20000
#define GG 300
#define CC 80
#define KK 4
#define MAXPOS 128
#define CAP 512          // anchors per (b,class): mean 250, sigma 15.7
#define GCAP 64          // gts per (b,class): mean 3.75
#define LIM 4096         // stored-IoU matrix capacity (u32)
#define IPB 250          // ints per scatter slice (250 * 80 = NN)
#define NBLK (BB * CC)   // 640 blocks, all co-resident (740 slots at occ 5)
#define T_HIGH_F 0.7f

__device__ __forceinline__ unsigned encf(float f) {
    unsigned u = __float_as_uint(f);
    return (u & 0x80000000u) ? ~u : (u | 0x80000000u);
}
__device__ __forceinline__ float decf(unsigned e) {   // exact for iou >= 0
    return __uint_as_float(e & 0x7fffffffu);
}

// ---------------- global scratch ----------------
__device__ int g_cursor[BB * CC];      // zero-init; owner block re-zeroes each run
__device__ int g_bidx[BB * CC * CAP];
__device__ unsigned long long g_bar;   // monotone barrier counter (never reset)

// IoU split: anchor conversion hoisted out of the per-gt loop. Every op is an
// explicit *_rn intrinsic -> no FMA contraction -> the per-pair op sequence is
// identical everywhere (the low-quality-match test is exact float equality).
__device__ __forceinline__ void aconv(float4 a, float& ax1, float& ay1,
                                      float& ax2, float& ay2, float& aarea) {
    float hw = __fmul_rn(0.5f, a.z);
    float hh = __fmul_rn(0.5f, a.w);
    ax1 = __fsub_rn(a.x, hw); ay1 = __fsub_rn(a.y, hh);
    ax2 = __fadd_rn(a.x, hw); ay2 = __fadd_rn(a.y, hh);
    aarea = __fmul_rn(__fsub_rn(ax2, ax1), __fsub_rn(ay2, ay1));
}
__device__ __forceinline__ float iou_core(float4 g, float garea,
                                          float ax1, float ay1, float ax2,
                                          float ay2, float aarea) {
    float ltx = fmaxf(g.x, ax1), lty = fmaxf(g.y, ay1);
    float rbx = fminf(g.z, ax2), rby = fminf(g.w, ay2);
    float w = fmaxf(__fsub_rn(rbx, ltx), 0.0f);
    float h = fmaxf(__fsub_rn(rby, lty), 0.0f);
    float inter = __fmul_rn(w, h);
    float uni = __fsub_rn(__fadd_rn(garea, aarea), inter);
    return __fdiv_rn(inter, uni);
}
__device__ __forceinline__ float iou_ga(float4 g, float garea, float4 a) {
    float ax1, ay1, ax2, ay2, aarea;
    aconv(a, ax1, ay1, ax2, ay2, aarea);
    return iou_core(g, garea, ax1, ay1, ax2, ay2, aarea);
}

__device__ __forceinline__ bool better(float v1, int i1, float v2, int i2) {
    return (v1 > v2) || (v1 == v2 && i1 < i2);
}

// compare-exchange: keep the better pair in (va, ia)  [static indices only]
#define CASX(va, ia, vb, ib) do {                                   \
        bool _sw = better(vb, ib, va, ia);                          \
        float _tv = _sw ? vb : va; vb = _sw ? va : vb; va = _tv;    \
        int   _ti = _sw ? ib : ia; ib = _sw ? ia : ib; ia = _ti;    \
    } while (0)

__global__ void __launch_bounds__(256, 5)
k_fused(const float* __restrict__ anchors, const int* __restrict__ prompt_inds,
        const int* __restrict__ tgt_labels, const float* __restrict__ tgt_boxes,
        float* __restrict__ out) {
    const int bid = blockIdx.x;            // 0 .. NBLK-1
    const int b = bid / CC, c = bid % CC;  // assign role; c also = scatter slice
    const int t = threadIdx.x;
    const int lane = t & 31, wid = t >> 5;

    __shared__ int      s_cnt[CC], s_base[CC];
    __shared__ int      s_gc, s_pos, s_thr;
    __shared__ int      s_idx[CAP];
    __shared__ unsigned s_iou[LIM];        // encoded IoU, [i * S + j], S = Gc|1
    __shared__ unsigned char s_posf[CAP];
    __shared__ unsigned char s_bestj[CAP];
    __shared__ int      s_gid[GCAP];
    __shared__ float4   s_gxy[GCAP];
    __shared__ float    s_garea[GCAP];
    __shared__ unsigned s_gmax[GCAP];

    if (t < CC) s_cnt[t] = 0;
    if (t == 0) { s_gc = 0; s_pos = 0; s_thr = NN - 1; }
    __syncthreads();

    // ---- Phase S: scatter this block's 250-int slice into (b,class) bins ----
    int mycls = -1, myrank = 0;
    const int myn = c * IPB + t;           // anchor id within image b
    if (t < IPB) {
        mycls = prompt_inds[b * NN + myn];
        myrank = atomicAdd(&s_cnt[mycls], 1);
    }
    __syncthreads();
    if (t < CC && s_cnt[t] > 0)
        s_base[t] = atomicAdd(&g_cursor[b * CC + t], s_cnt[t]);
    __syncthreads();
    if (t < IPB) {
        int q = s_base[mycls] + myrank;
        if (q < CAP) g_bidx[(b * CC + mycls) * CAP + q] = myn;
    }

    // ---- Phase G: gt list (independent of scatter; hides barrier skew).
    //      Unordered compaction: every later tie-break uses explicit gt id. ----
    for (int g = t; g < GG; g += 256) {
        if (tgt_labels[b * GG + g] == c) {
            int j = atomicAdd(&s_gc, 1);
            if (j < GCAP) {
                float4 bx = ((const float4*)tgt_boxes)[b * GG + g];
                float hw = __fmul_rn(0.5f, bx.z), hh = __fmul_rn(0.5f, bx.w);
                float4 xy = make_float4(__fsub_rn(bx.x, hw), __fsub_rn(bx.y, hh),
                                        __fadd_rn(bx.x, hw), __fadd_rn(bx.y, hh));
                s_gid[j]   = g;
                s_gxy[j]   = xy;
                s_garea[j] = __fmul_rn(__fsub_rn(xy.z, xy.x), __fsub_rn(xy.w, xy.y));
            }
        }
    }

    // ---- grid barrier: monotone counter, all 640 blocks co-resident ----
    __threadfence();
    __syncthreads();
    if (t == 0) {
        unsigned long long old = atomicAdd(&g_bar, 1ull);
        unsigned long long target = (old / NBLK + 1ull) * (unsigned long long)NBLK;
        while (*(volatile unsigned long long*)&g_bar < target) { __nanosleep(32); }
        __threadfence();
    }
    __syncthreads();

    // ---- Phase A: load this bin's indices ----
    const int m = min(g_cursor[bid], CAP);
    for (int i = t; i < m; i += 256)
        s_idx[i] = g_bidx[bid * CAP + i];
    __syncthreads();
    if (t == 0) g_cursor[bid] = 0;     // owner-only; reset for next replay

    const int Gc = min(s_gc, GCAP);
    if (Gc == 0) return;               // safe: past the barrier

    const int S = Gc | 1;              // odd stride -> conflict-free smem
    const bool stored = (m * S <= LIM);

    // ---- row scan: anchor converted ONCE; per-pair IoU stored; NO atomics ----
    float best0 = -1.0f, best1 = -1.0f;
#define ROW_SCAN(ii, bestv) do {                                              \
        float4 a = ((const float4*)anchors)[b * NN + s_idx[ii]];              \
        float ax1, ay1, ax2, ay2, aarea;                                      \
        aconv(a, ax1, ay1, ax2, ay2, aarea);                                  \
        float bv = -1.0f;                                                     \
        int bj = 0, bgid = 0x7fffffff;                                        \
        for (int j = 0; j < Gc; j++) {                                        \
            float v = iou_core(s_gxy[j], s_garea[j], ax1, ay1, ax2, ay2, aarea); \
            if (stored) s_iou[(ii) * S + j] = encf(v);                        \
            int gj = s_gid[j];                                                \
            if (v > bv || (v == bv && gj < bgid)) { bv = v; bj = j; bgid = gj; } \
        }                                                                     \
        bestv = bv;                                                           \
        s_bestj[ii] = (unsigned char)bj;                                      \
    } while (0)
    if (t < m)       ROW_SCAN(t, best0);
    if (t + 256 < m) ROW_SCAN(t + 256, best1);
#undef ROW_SCAN
    __syncthreads();

    // ---- column max: warp per gt, conflict-free strided LDS + warp reduce ----
    for (int j = wid; j < Gc; j += 8) {
        unsigned mx = 0u;
        if (stored) {
            for (int i = lane; i < m; i += 32)
                mx = max(mx, s_iou[i * S + j]);
        } else {                        // fallback (never hit): recompute
            float4 gx = s_gxy[j];
            float ga = s_garea[j];
            for (int i = lane; i < m; i += 32) {
                float4 a = ((const float4*)anchors)[b * NN + s_idx[i]];
                mx = max(mx, encf(iou_ga(gx, ga, a)));
            }
        }
        mx = __reduce_max_sync(0xffffffffu, mx);
        if (lane == 0) s_gmax[j] = mx;
    }
    __syncthreads();

    // ---- positivity: flags + warp-aggregated total (no per-gt atomics) ----
#define POS_SCAN(ii, bestv, act) do {                                         \
        bool pos = false;                                                     \
        if (act) {                                                            \
            pos = (bestv >= T_HIGH_F);                                        \
            if (!pos) {                                                       \
                if (stored) {                                                 \
                    for (int j = 0; j < Gc; j++)                              \
                        if (s_iou[(ii) * S + j] == s_gmax[j]) { pos = true; break; } \
                } else {                                                      \
                    float4 a = ((const float4*)anchors)[b * NN + s_idx[ii]];  \
                    unsigned eb = encf(bestv);                                \
                    for (int j = 0; j < Gc; j++) {                            \
                        unsigned gm = s_gmax[j];                              \
                        if (eb >= gm &&                                       \
                            encf(iou_ga(s_gxy[j], s_garea[j], a)) == gm) {    \
                            pos = true; break; }                              \
                    }                                                         \
                }                                                             \
            }                                                                 \
            s_posf[ii] = pos ? 1 : 0;                                         \
        }                                                                     \
        unsigned bl = __ballot_sync(0xffffffffu, pos);                        \
        if (lane == 0 && bl) atomicAdd(&s_pos, __popc(bl));                   \
    } while (0)
    POS_SCAN(t, best0, (t < m));
    POS_SCAN(t + 256, best1, (t + 256 < m));
#undef POS_SCAN
    __syncthreads();

    // ---- rare MAX_POS fixup: warp 0 binary-searches the rank-128 positive
    //      anchor id; threshold applied inline during the top-k count ----
    if (s_pos > MAXPOS && wid == 0) {
        int lo = 0, hi = NN - 1;
        while (lo < hi) {
            int mid = (lo + hi) >> 1;
            int cnt = 0;
            for (int i = lane; i < m; i += 32)
                if (s_posf[i] && s_idx[i] <= mid) cnt++;
            cnt = __reduce_add_sync(0xffffffffu, cnt);
            if (cnt >= MAXPOS) hi = mid; else lo = mid + 1;
        }
        if (lane == 0) s_thr = lo;
    }
    __syncthreads();
    const int thr = s_thr;

    // ---- top-4 + inline per-gt positive count: one warp per gt ----
    const int P = BB * GG * KK;
    for (int j = wid; j < Gc; j += 8) {
        float v0 = -1e30f, v1 = -1e30f, v2 = -1e30f, v3 = -1e30f;
        int   i0 = 0x7fffffff, i1 = 0x7fffffff, i2 = 0x7fffffff, i3 = 0x7fffffff;
        int   cnt = 0;
#define INSERT(val, n) do {                                                   \
        if (better(val, n, v3, i3)) {                                         \
            v3 = val; i3 = n;                                                 \
            if (better(v3, i3, v2, i2)) { float tv=v2;int ti=i2; v2=v3;i2=i3; v3=tv;i3=ti; } \
            if (better(v2, i2, v1, i1)) { float tv=v1;int ti=i1; v1=v2;i1=i2; v2=tv;i2=ti; } \
            if (better(v1, i1, v0, i0)) { float tv=v0;int ti=i0; v0=v1;i0=i1; v1=tv;i1=ti; } \
        }                                                                     \
    } while (0)
        if (stored) {
            for (int i = lane; i < m; i += 32) {
                float val = decf(s_iou[i * S + j]);
                int n = s_idx[i];
                if (s_posf[i] && s_bestj[i] == j && n <= thr) cnt++;
                INSERT(val, n);
            }
        } else {
            float4 gx = s_gxy[j];
            float ga = s_garea[j];
            for (int i = lane; i < m; i += 32) {
                float4 a = ((const float4*)anchors)[b * NN + s_idx[i]];
                float val = iou_ga(gx, ga, a);
                int n = s_idx[i];
                if (s_posf[i] && s_bestj[i] == j && n <= thr) cnt++;
                INSERT(val, n);
            }
        }
#undef INSERT
        cnt = __reduce_add_sync(0xffffffffu, cnt);
        // butterfly merge: bitonic half-cleaner + 4-sort, all static indices
#pragma unroll
        for (int off = 16; off >= 1; off >>= 1) {
            float b0 = __shfl_xor_sync(0xffffffffu, v0, off);
            float b1 = __shfl_xor_sync(0xffffffffu, v1, off);
            float b2 = __shfl_xor_sync(0xffffffffu, v2, off);
            float b3 = __shfl_xor_sync(0xffffffffu, v3, off);
            int   c0 = __shfl_xor_sync(0xffffffffu, i0, off);
            int   c1 = __shfl_xor_sync(0xffffffffu, i1, off);
            int   c2 = __shfl_xor_sync(0xffffffffu, i2, off);
            int   c3 = __shfl_xor_sync(0xffffffffu, i3, off);
            if (better(b3, c3, v0, i0)) { v0 = b3; i0 = c3; }
            if (better(b2, c2, v1, i1)) { v1 = b2; i1 = c2; }
            if (better(b1, c1, v2, i2)) { v2 = b1; i2 = c1; }
            if (better(b0, c0, v3, i3)) { v3 = b0; i3 = c0; }
            CASX(v0, i0, v2, i2);
            CASX(v1, i1, v3, i3);
            CASX(v0, i0, v1, i1);
            CASX(v2, i2, v3, i3);
        }
        int kk = min(cnt, KK);
        int g = s_gid[j];
        if (lane == 0) {
            int o = (b * GG + g) * KK;
            float ov[KK] = {v0, v1, v2, v3};
            int   oi[KK] = {i0, i1, i2, i3};
#pragma unroll
            for (int k = 0; k < KK; k++) {
                bool valid = (k < kk);
                out[o + k]         = valid ? (float)oi[k] : -1.0f;
                out[P + o + k]     = valid ? (float)g     : -1.0f;
                out[2 * P + o + k] = valid ? 1.0f : 0.0f;
                out[3 * P + o + k] = valid ? ov[k] : 0.0f;
            }
        }
    }
}

// ---------------- launch: single fused kernel ----------------
extern "C" void kernel_launch(void* const* d_in, const int* in_sizes, int n_in,
                              void* d_out, int out_size) {
    (void)in_sizes; (void)n_in; (void)out_size;
    const float* anchors     = (const float*)d_in[2];
    const int*   prompt_inds = (const int*)d_in[3];
    const int*   tgt_labels  = (const int*)d_in[4];
    const float* tgt_boxes   = (const float*)d_in[5];
    float* out = (float*)d_out;

    k_fused<<<NBLK, 256>>>(anchors, prompt_inds, tgt_labels, tgt_boxes, out);
}